// round 1
// baseline (speedup 1.0000x reference)
#include <cuda_runtime.h>
#include <math.h>

#define D   128
#define Bn  4
#define NSn 10000
#define NTn 10000
#define En  160000
#define Kc  16

// ---------------- scratch (static __device__, allocation-free) ----------------
__device__ float g_Ps  [Bn * NSn * D];   // src @ W_s2e
__device__ float g_Pt  [Bn * NTn * D];   // tgt @ W_t2e
__device__ float g_Ptt [Bn * NTn * D];   // tgt @ W_t2t
__device__ float g_db  [Bn * En  * D];   // d_bond (post-LN)
__device__ float g_red [Bn * NTn * D];   // bond_reduce

// ---------------- shared GEMM core: 64 rows x 128 cols per block ----------------
// 256 threads; tx=tid&31 covers cols tx*4..tx*4+3, ty=tid>>5 covers rows ty*8..ty*8+7
__device__ __forceinline__ void load_W(float* Ws, const float* __restrict__ W, int tid) {
    #pragma unroll
    for (int i = tid; i < D * D / 4; i += 256)
        ((float4*)Ws)[i] = ((const float4*)W)[i];
}
__device__ __forceinline__ void load_X(float* Xs, const float* __restrict__ X, int tid) {
    #pragma unroll
    for (int i = tid; i < 64 * D / 4; i += 256)
        ((float4*)Xs)[i] = ((const float4*)X)[i];
}

__device__ __forceinline__ void gemm_tile(const float* __restrict__ Ws,
                                          const float* __restrict__ Xs,
                                          float acc[8][4], int tx, int ty) {
    const float4* W4 = (const float4*)Ws;
    const float4* X4 = (const float4*)Xs;
    #pragma unroll 2
    for (int k = 0; k < D; k += 4) {
        int kq = k >> 2;
        float4 wv[4];
        wv[0] = W4[(k + 0) * 32 + tx];
        wv[1] = W4[(k + 1) * 32 + tx];
        wv[2] = W4[(k + 2) * 32 + tx];
        wv[3] = W4[(k + 3) * 32 + tx];
        #pragma unroll
        for (int r = 0; r < 8; r++) {
            float4 xv = X4[(ty * 8 + r) * 32 + kq];
            float xs4[4] = {xv.x, xv.y, xv.z, xv.w};
            #pragma unroll
            for (int kk = 0; kk < 4; kk++) {
                float4 w = wv[kk];
                acc[r][0] += xs4[kk] * w.x;
                acc[r][1] += xs4[kk] * w.y;
                acc[r][2] += xs4[kk] * w.z;
                acc[r][3] += xs4[kk] * w.w;
            }
        }
    }
}

// silu + warp-LayerNorm over one 128-wide row distributed across 32 lanes (4 vals/lane)
__device__ __forceinline__ void silu_ln(float v[4], const float gg[4], const float bb[4],
                                        float out[4]) {
    #pragma unroll
    for (int c = 0; c < 4; c++)
        v[c] = v[c] / (1.0f + __expf(-v[c]));
    float s1 = v[0] + v[1] + v[2] + v[3];
    float s2 = v[0]*v[0] + v[1]*v[1] + v[2]*v[2] + v[3]*v[3];
    #pragma unroll
    for (int o = 16; o > 0; o >>= 1) {
        s1 += __shfl_xor_sync(0xFFFFFFFFu, s1, o);
        s2 += __shfl_xor_sync(0xFFFFFFFFu, s2, o);
    }
    float m   = s1 * (1.0f / D);
    float var = fmaxf(s2 * (1.0f / D) - m * m, 0.0f);
    float rs  = rsqrtf(var + 1e-5f);
    #pragma unroll
    for (int c = 0; c < 4; c++)
        out[c] = (v[c] - m) * rs * gg[c] + bb[c];
}

// ---------------- kernel 1: src @ W_s2e -> g_Ps ----------------
__global__ __launch_bounds__(256) void proj_src_kernel(const float* __restrict__ src,
                                                       const float* __restrict__ W) {
    extern __shared__ float sm[];
    float* Ws = sm;
    float* Xs = sm + D * D;
    int tid = threadIdx.x, tx = tid & 31, ty = tid >> 5;
    int row0 = blockIdx.x * 64;
    load_W(Ws, W, tid);
    load_X(Xs, src + (size_t)row0 * D, tid);
    __syncthreads();
    float acc[8][4] = {};
    gemm_tile(Ws, Xs, acc, tx, ty);
    #pragma unroll
    for (int r = 0; r < 8; r++) {
        float4 v = {acc[r][0], acc[r][1], acc[r][2], acc[r][3]};
        *(float4*)(g_Ps + (size_t)(row0 + ty * 8 + r) * D + tx * 4) = v;
    }
}

// ---------------- kernel 2: tgt @ W_t2e -> g_Pt ; tgt @ W_t2t -> g_Ptt ----------------
__global__ __launch_bounds__(256) void proj_tgt_dual_kernel(const float* __restrict__ tgt,
                                                            const float* __restrict__ W1,
                                                            const float* __restrict__ W2) {
    extern __shared__ float sm[];
    float* Ws1 = sm;
    float* Ws2 = sm + D * D;
    float* Xs  = sm + 2 * D * D;
    int tid = threadIdx.x, tx = tid & 31, ty = tid >> 5;
    int row0 = blockIdx.x * 64;
    load_W(Ws1, W1, tid);
    load_W(Ws2, W2, tid);
    load_X(Xs, tgt + (size_t)row0 * D, tid);
    __syncthreads();
    {
        float acc[8][4] = {};
        gemm_tile(Ws1, Xs, acc, tx, ty);
        #pragma unroll
        for (int r = 0; r < 8; r++) {
            float4 v = {acc[r][0], acc[r][1], acc[r][2], acc[r][3]};
            *(float4*)(g_Pt + (size_t)(row0 + ty * 8 + r) * D + tx * 4) = v;
        }
    }
    {
        float acc[8][4] = {};
        gemm_tile(Ws2, Xs, acc, tx, ty);
        #pragma unroll
        for (int r = 0; r < 8; r++) {
            float4 v = {acc[r][0], acc[r][1], acc[r][2], acc[r][3]};
            *(float4*)(g_Ptt + (size_t)(row0 + ty * 8 + r) * D + tx * 4) = v;
        }
    }
}

// ---------------- kernel 3: d_bond = LN(silu(bond@W_e2e + gather(Ps) + gather(Pt))) ----------------
__global__ __launch_bounds__(256) void bond_kernel(const float* __restrict__ bond,
                                                   const float* __restrict__ W,
                                                   const float* __restrict__ g1,
                                                   const float* __restrict__ b1,
                                                   const int* __restrict__ src_order,
                                                   const int* __restrict__ tgt_order,
                                                   float* __restrict__ out0) {
    extern __shared__ float sm[];
    float* Ws = sm;
    float* Xs = sm + D * D;
    int tid = threadIdx.x, tx = tid & 31, ty = tid >> 5;
    int row0 = blockIdx.x * 64;          // global row in [0, B*E)
    int b    = row0 / En;                // tile never crosses batch (E % 64 == 0)
    load_W(Ws, W, tid);
    load_X(Xs, bond + (size_t)row0 * D, tid);
    __syncthreads();
    float acc[8][4] = {};
    gemm_tile(Ws, Xs, acc, tx, ty);

    float gg[4], bb[4];
    #pragma unroll
    for (int c = 0; c < 4; c++) { gg[c] = g1[tx * 4 + c]; bb[c] = b1[tx * 4 + c]; }

    #pragma unroll
    for (int r = 0; r < 8; r++) {
        int row = row0 + ty * 8 + r;
        int e   = row - b * En;
        int so  = src_order[e];
        int to  = tgt_order[e];
        float4 ps = *(const float4*)(g_Ps + ((size_t)b * NSn + so) * D + tx * 4);
        float4 pt = *(const float4*)(g_Pt + ((size_t)b * NTn + to) * D + tx * 4);
        float v[4];
        v[0] = acc[r][0] + ps.x + pt.x;
        v[1] = acc[r][1] + ps.y + pt.y;
        v[2] = acc[r][2] + ps.z + pt.z;
        v[3] = acc[r][3] + ps.w + pt.w;
        float d[4];
        silu_ln(v, gg, bb, d);
        float4 db = {d[0], d[1], d[2], d[3]};
        float4 xin = *(const float4*)(Xs + (ty * 8 + r) * D + tx * 4);
        float4 o0 = {xin.x + d[0], xin.y + d[1], xin.z + d[2], xin.w + d[3]};
        *(float4*)(g_db + (size_t)row * D + tx * 4) = db;
        *(float4*)(out0 + (size_t)row * D + tx * 4) = o0;
    }
}

// ---------------- kernel 4: bond_reduce = mean_k(coef * d_bond[edge_order]) ----------------
__global__ __launch_bounds__(256) void reduce_kernel(const int* __restrict__ edge_order,
                                                     const float* __restrict__ coef) {
    int tid  = threadIdx.x;
    int lane = tid & 31;
    int node = (blockIdx.x * blockDim.x + tid) >> 5;   // [0, B*NT)
    int b = node / NTn;
    int t = node - b * NTn;

    // preload per-node indices/coefs into lanes 0..15, broadcast via shfl
    int   e_l = 0;
    float c_l = 0.0f;
    if (lane < Kc) {
        e_l = edge_order[t * Kc + lane];
        c_l = coef[t * Kc + lane];
    }
    float4 acc = {0.f, 0.f, 0.f, 0.f};
    #pragma unroll
    for (int k = 0; k < Kc; k++) {
        int   e = __shfl_sync(0xFFFFFFFFu, e_l, k);
        float c = __shfl_sync(0xFFFFFFFFu, c_l, k);
        float4 v = *(const float4*)(g_db + ((size_t)b * En + e) * D + lane * 4);
        acc.x += c * v.x;
        acc.y += c * v.y;
        acc.z += c * v.z;
        acc.w += c * v.w;
    }
    const float inv = 1.0f / Kc;
    acc.x *= inv; acc.y *= inv; acc.z *= inv; acc.w *= inv;
    *(float4*)(g_red + (size_t)node * D + lane * 4) = acc;
}

// ---------------- kernel 5: d_tgt = LN(silu(red@W_e2t + Ptt)) ; out = tgt + d_tgt ----------------
__global__ __launch_bounds__(256) void tgt_kernel(const float* __restrict__ tgt,
                                                  const float* __restrict__ W,
                                                  const float* __restrict__ g2,
                                                  const float* __restrict__ b2,
                                                  float* __restrict__ out2) {
    extern __shared__ float sm[];
    float* Ws = sm;
    float* Xs = sm + D * D;
    int tid = threadIdx.x, tx = tid & 31, ty = tid >> 5;
    int row0 = blockIdx.x * 64;          // row in [0, B*NT)
    load_W(Ws, W, tid);
    load_X(Xs, g_red + (size_t)row0 * D, tid);
    __syncthreads();
    float acc[8][4] = {};
    gemm_tile(Ws, Xs, acc, tx, ty);

    float gg[4], bb[4];
    #pragma unroll
    for (int c = 0; c < 4; c++) { gg[c] = g2[tx * 4 + c]; bb[c] = b2[tx * 4 + c]; }

    #pragma unroll
    for (int r = 0; r < 8; r++) {
        int row = row0 + ty * 8 + r;
        float4 pt = *(const float4*)(g_Ptt + (size_t)row * D + tx * 4);
        float v[4];
        v[0] = acc[r][0] + pt.x;
        v[1] = acc[r][1] + pt.y;
        v[2] = acc[r][2] + pt.z;
        v[3] = acc[r][3] + pt.w;
        float d[4];
        silu_ln(v, gg, bb, d);
        float4 tin = *(const float4*)(tgt + (size_t)row * D + tx * 4);
        float4 o2 = {tin.x + d[0], tin.y + d[1], tin.z + d[2], tin.w + d[3]};
        *(float4*)(out2 + (size_t)row * D + tx * 4) = o2;
    }
}

// ---------------- launch ----------------
extern "C" void kernel_launch(void* const* d_in, const int* in_sizes, int n_in,
                              void* d_out, int out_size) {
    const float* bond  = (const float*)d_in[0];
    const float* src   = (const float*)d_in[1];
    const float* tgt   = (const float*)d_in[2];
    const float* W_s2e = (const float*)d_in[3];
    const float* W_t2e = (const float*)d_in[4];
    const float* W_e2e = (const float*)d_in[5];
    const float* ln1_g = (const float*)d_in[6];
    const float* ln1_b = (const float*)d_in[7];
    const float* W_e2t = (const float*)d_in[8];
    const float* W_t2t = (const float*)d_in[9];
    const float* ln2_g = (const float*)d_in[10];
    const float* ln2_b = (const float*)d_in[11];
    const float* coef  = (const float*)d_in[12];
    const int*   so    = (const int*)d_in[13];
    const int*   to    = (const int*)d_in[14];
    const int*   eo    = (const int*)d_in[15];

    float* out  = (float*)d_out;
    float* out0 = out;                                   // bond + d_bond   [B,E,D]
    float* out1 = out0 + (size_t)Bn * En * D;            // src passthrough [B,NS,D]
    float* out2 = out1 + (size_t)Bn * NSn * D;           // tgt + d_tgt     [B,NT,D]

    const int SM1 = (D * D + 64 * D) * sizeof(float);        //  96 KB
    const int SM2 = (2 * D * D + 64 * D) * sizeof(float);    // 160 KB
    cudaFuncSetAttribute(proj_src_kernel,      cudaFuncAttributeMaxDynamicSharedMemorySize, SM1);
    cudaFuncSetAttribute(proj_tgt_dual_kernel, cudaFuncAttributeMaxDynamicSharedMemorySize, SM2);
    cudaFuncSetAttribute(bond_kernel,          cudaFuncAttributeMaxDynamicSharedMemorySize, SM1);
    cudaFuncSetAttribute(tgt_kernel,           cudaFuncAttributeMaxDynamicSharedMemorySize, SM1);

    // node projections (independent)
    proj_src_kernel<<<(Bn * NSn) / 64, 256, SM1>>>(src, W_s2e);
    proj_tgt_dual_kernel<<<(Bn * NTn) / 64, 256, SM2>>>(tgt, W_t2e, W_t2t);

    // src passthrough
    cudaMemcpyAsync(out1, src, (size_t)Bn * NSn * D * sizeof(float),
                    cudaMemcpyDeviceToDevice, 0);

    // node2bond + silu + LN
    bond_kernel<<<(Bn * En) / 64, 256, SM1>>>(bond, W_e2e, ln1_g, ln1_b, so, to, out0);

    // bond2node weighted mean
    reduce_kernel<<<(Bn * NTn) / 8, 256>>>(eo, coef);

    // target update + silu + LN
    tgt_kernel<<<(Bn * NTn) / 64, 256, SM1>>>(tgt, W_e2t, ln2_g, ln2_b, out2);
}

// round 2
// speedup vs baseline: 1.4928x; 1.4928x over previous
#include <cuda_runtime.h>
#include <cuda_bf16.h>
#include <math.h>
#include <stdint.h>

#define D    128
#define Bn   4
#define NSn  10000
#define NTn  10000
#define En   160000
#define Kc   16
#define LDS_T 136   // padded bf16 row length in smem (272B, 16B-aligned, ldmatrix conflict-free)
#define LDC   132   // padded fp32 C row (breaks 128-word bank wrap)

// ---------------- scratch (static __device__, allocation-free) ----------------
__device__ float g_Ps  [Bn * NSn * D];   // src @ W_s2e
__device__ float g_Pt  [Bn * NTn * D];   // tgt @ W_t2e
__device__ float g_Ptt [Bn * NTn * D];   // tgt @ W_t2t
__device__ float g_db  [Bn * En  * D];   // d_bond (post-LN)
__device__ float g_red [Bn * NTn * D];   // bond_reduce
// pre-split weights: 0=W_s2e 1=W_t2e 2=W_e2e 3=W_e2t 4=W_t2t
__device__ __nv_bfloat16 g_Wh[5 * D * D];
__device__ __nv_bfloat16 g_Wl[5 * D * D];

// ---------------- PTX helpers ----------------
__device__ __forceinline__ uint32_t smem_u32(const void* p) {
    return (uint32_t)__cvta_generic_to_shared(p);
}
__device__ __forceinline__ void ldsm4(uint32_t a, uint32_t& r0, uint32_t& r1, uint32_t& r2, uint32_t& r3) {
    asm volatile("ldmatrix.sync.aligned.m8n8.x4.shared.b16 {%0,%1,%2,%3}, [%4];"
                 : "=r"(r0), "=r"(r1), "=r"(r2), "=r"(r3) : "r"(a));
}
__device__ __forceinline__ void ldsm4t(uint32_t a, uint32_t& r0, uint32_t& r1, uint32_t& r2, uint32_t& r3) {
    asm volatile("ldmatrix.sync.aligned.m8n8.x4.trans.shared.b16 {%0,%1,%2,%3}, [%4];"
                 : "=r"(r0), "=r"(r1), "=r"(r2), "=r"(r3) : "r"(a));
}
__device__ __forceinline__ void mma16816(float c[4], uint32_t a0, uint32_t a1, uint32_t a2, uint32_t a3,
                                         uint32_t b0, uint32_t b1) {
    asm volatile("mma.sync.aligned.m16n8k16.row.col.f32.bf16.bf16.f32 "
                 "{%0,%1,%2,%3},{%4,%5,%6,%7},{%8,%9},{%0,%1,%2,%3};"
                 : "+f"(c[0]), "+f"(c[1]), "+f"(c[2]), "+f"(c[3])
                 : "r"(a0), "r"(a1), "r"(a2), "r"(a3), "r"(b0), "r"(b1));
}

// ---------------- weight pre-split kernel ----------------
__global__ __launch_bounds__(256) void prep_w_kernel(const float* __restrict__ W0,
                                                     const float* __restrict__ W1,
                                                     const float* __restrict__ W2,
                                                     const float* __restrict__ W3,
                                                     const float* __restrict__ W4) {
    int i = blockIdx.x * 256 + threadIdx.x;      // 0 .. 5*16384-1
    int w = i >> 14, j = i & (D * D - 1);
    const float* W = (w == 0) ? W0 : (w == 1) ? W1 : (w == 2) ? W2 : (w == 3) ? W3 : W4;
    float x = W[j];
    __nv_bfloat16 h = __float2bfloat16(x);
    float hf = __bfloat162float(h);
    g_Wh[i] = h;
    g_Wl[i] = __float2bfloat16(x - hf);
}

// ---------------- tile loads ----------------
__device__ __forceinline__ void load_W_tile(__nv_bfloat16* Wh, __nv_bfloat16* Wl, int widx, int tid) {
    const __nv_bfloat16* gh = g_Wh + widx * D * D;
    const __nv_bfloat16* gl = g_Wl + widx * D * D;
    #pragma unroll
    for (int i = tid; i < D * 16; i += 256) {      // uint4 = 8 bf16; 128*128/8 = 2048
        int r = i >> 4, c = (i & 15) * 8;
        *(uint4*)(Wh + r * LDS_T + c) = *(const uint4*)(gh + r * D + c);
        *(uint4*)(Wl + r * LDS_T + c) = *(const uint4*)(gl + r * D + c);
    }
}
__device__ __forceinline__ void load_X_split(__nv_bfloat16* Xh, __nv_bfloat16* Xl,
                                             const float* __restrict__ Xg, int tid) {
    #pragma unroll
    for (int i = tid; i < 64 * 32; i += 256) {
        int r = i >> 5, c = (i & 31) * 4;
        float4 v = *(const float4*)(Xg + (size_t)r * D + c);
        __nv_bfloat16 hx = __float2bfloat16(v.x), hy = __float2bfloat16(v.y);
        __nv_bfloat16 hz = __float2bfloat16(v.z), hw = __float2bfloat16(v.w);
        __nv_bfloat16 lx = __float2bfloat16(v.x - __bfloat162float(hx));
        __nv_bfloat16 ly = __float2bfloat16(v.y - __bfloat162float(hy));
        __nv_bfloat16 lz = __float2bfloat16(v.z - __bfloat162float(hz));
        __nv_bfloat16 lw = __float2bfloat16(v.w - __bfloat162float(hw));
        __nv_bfloat16* ph = Xh + r * LDS_T + c;
        __nv_bfloat16* pl = Xl + r * LDS_T + c;
        *(__nv_bfloat162*)(ph)     = __nv_bfloat162(hx, hy);
        *(__nv_bfloat162*)(ph + 2) = __nv_bfloat162(hz, hw);
        *(__nv_bfloat162*)(pl)     = __nv_bfloat162(lx, ly);
        *(__nv_bfloat162*)(pl + 2) = __nv_bfloat162(lz, lw);
    }
}

// ---------------- MMA GEMM core: 64x128 tile, 8 warps (4 row-groups x 2 col-groups) ----------------
__device__ __forceinline__ void gemm_mma(const __nv_bfloat16* Xh, const __nv_bfloat16* Xl,
                                         const __nv_bfloat16* Wh, const __nv_bfloat16* Wl,
                                         int tid, float acc[8][4]) {
    int lane = tid & 31, w = tid >> 5;
    int rg = (w & 3) * 16, cg = (w >> 2) * 64;
    #pragma unroll
    for (int i = 0; i < 8; i++)
        #pragma unroll
        for (int j = 0; j < 4; j++) acc[i][j] = 0.0f;

    int l7 = lane & 7, lm = lane >> 3;
    int a_row    = rg + l7 + ((lm & 1) << 3);
    int a_coladd = (lm >> 1) << 3;
    uint32_t aH = smem_u32(Xh + a_row * LDS_T + a_coladd);
    uint32_t aL = smem_u32(Xl + a_row * LDS_T + a_coladd);
    int b_krow   = l7 + ((lm & 1) << 3);
    int b_coladd = (lm >> 1) << 3;
    uint32_t bH[4], bL[4];
    #pragma unroll
    for (int nr = 0; nr < 4; nr++) {
        int col = cg + nr * 16 + b_coladd;
        bH[nr] = smem_u32(Wh + b_krow * LDS_T + col);
        bL[nr] = smem_u32(Wl + b_krow * LDS_T + col);
    }

    #pragma unroll
    for (int k0 = 0; k0 < D; k0 += 16) {
        uint32_t ah0, ah1, ah2, ah3, al0, al1, al2, al3;
        ldsm4(aH + k0 * 2, ah0, ah1, ah2, ah3);
        ldsm4(aL + k0 * 2, al0, al1, al2, al3);
        uint32_t koff = (uint32_t)(k0 * LDS_T * 2);
        #pragma unroll
        for (int nr = 0; nr < 4; nr++) {
            uint32_t bh0, bh1, bh2, bh3, bl0, bl1, bl2, bl3;
            ldsm4t(bH[nr] + koff, bh0, bh1, bh2, bh3);
            ldsm4t(bL[nr] + koff, bl0, bl1, bl2, bl3);
            mma16816(acc[2 * nr],     ah0, ah1, ah2, ah3, bh0, bh1);
            mma16816(acc[2 * nr],     ah0, ah1, ah2, ah3, bl0, bl1);
            mma16816(acc[2 * nr],     al0, al1, al2, al3, bh0, bh1);
            mma16816(acc[2 * nr + 1], ah0, ah1, ah2, ah3, bh2, bh3);
            mma16816(acc[2 * nr + 1], ah0, ah1, ah2, ah3, bl2, bl3);
            mma16816(acc[2 * nr + 1], al0, al1, al2, al3, bh2, bh3);
        }
    }
}

__device__ __forceinline__ void stage_acc(float* Cs, const float acc[8][4], int tid) {
    int lane = tid & 31, w = tid >> 5;
    int rg = (w & 3) * 16, cg = (w >> 2) * 64;
    int gid = lane >> 2, tid4 = lane & 3;
    #pragma unroll
    for (int nt = 0; nt < 8; nt++) {
        int col = cg + nt * 8 + tid4 * 2;
        int row = rg + gid;
        *(float2*)(Cs + row * LDC + col)       = make_float2(acc[nt][0], acc[nt][1]);
        *(float2*)(Cs + (row + 8) * LDC + col) = make_float2(acc[nt][2], acc[nt][3]);
    }
}

// silu + warp-LayerNorm over one 128-wide row distributed across 32 lanes (4 vals/lane)
__device__ __forceinline__ void silu_ln(float v[4], const float gg[4], const float bb[4],
                                        float out[4]) {
    #pragma unroll
    for (int c = 0; c < 4; c++)
        v[c] = v[c] / (1.0f + __expf(-v[c]));
    float s1 = v[0] + v[1] + v[2] + v[3];
    float s2 = v[0]*v[0] + v[1]*v[1] + v[2]*v[2] + v[3]*v[3];
    #pragma unroll
    for (int o = 16; o > 0; o >>= 1) {
        s1 += __shfl_xor_sync(0xFFFFFFFFu, s1, o);
        s2 += __shfl_xor_sync(0xFFFFFFFFu, s2, o);
    }
    float m   = s1 * (1.0f / D);
    float var = fmaxf(s2 * (1.0f / D) - m * m, 0.0f);
    float rs  = rsqrtf(var + 1e-5f);
    #pragma unroll
    for (int c = 0; c < 4; c++)
        out[c] = (v[c] - m) * rs * gg[c] + bb[c];
}

// smem layouts
//  single-W:  [Xh 64*136][Xl 64*136][Wh 128*136][Wl 128*136]; Cs overlays Xh/Xl
#define SM_SINGLE ((2 * 64 * LDS_T + 2 * D * LDS_T) * 2)
//  dual-W:    [Xh][Xl][Wh1][Wl1][Wh2][Wl2]; Cs overlays Wh1
#define SM_DUAL   ((2 * 64 * LDS_T + 4 * D * LDS_T) * 2)

// ---------------- kernel 1: src @ W_s2e -> g_Ps ----------------
__global__ __launch_bounds__(256) void proj_src_kernel(const float* __restrict__ src) {
    extern __shared__ char sm[];
    __nv_bfloat16* Xh = (__nv_bfloat16*)sm;
    __nv_bfloat16* Xl = Xh + 64 * LDS_T;
    __nv_bfloat16* Wh = Xl + 64 * LDS_T;
    __nv_bfloat16* Wl = Wh + D * LDS_T;
    float* Cs = (float*)sm;
    int tid = threadIdx.x;
    int row0 = blockIdx.x * 64;
    load_W_tile(Wh, Wl, 0, tid);
    load_X_split(Xh, Xl, src + (size_t)row0 * D, tid);
    __syncthreads();
    float acc[8][4];
    gemm_mma(Xh, Xl, Wh, Wl, tid, acc);
    __syncthreads();
    stage_acc(Cs, acc, tid);
    __syncthreads();
    int tx = tid & 31, ty = tid >> 5;
    #pragma unroll
    for (int r = 0; r < 8; r++) {
        float4 v = *(float4*)(Cs + (ty * 8 + r) * LDC + tx * 4);
        *(float4*)(g_Ps + (size_t)(row0 + ty * 8 + r) * D + tx * 4) = v;
    }
}

// ---------------- kernel 2: tgt @ W_t2e -> g_Pt ; tgt @ W_t2t -> g_Ptt ----------------
__global__ __launch_bounds__(256) void proj_tgt_dual_kernel(const float* __restrict__ tgt) {
    extern __shared__ char sm[];
    __nv_bfloat16* Xh  = (__nv_bfloat16*)sm;
    __nv_bfloat16* Xl  = Xh + 64 * LDS_T;
    __nv_bfloat16* Wh1 = Xl + 64 * LDS_T;
    __nv_bfloat16* Wl1 = Wh1 + D * LDS_T;
    __nv_bfloat16* Wh2 = Wl1 + D * LDS_T;
    __nv_bfloat16* Wl2 = Wh2 + D * LDS_T;
    float* Cs = (float*)Wh1;   // overlays W1 after first GEMM
    int tid = threadIdx.x;
    int row0 = blockIdx.x * 64;
    load_W_tile(Wh1, Wl1, 1, tid);   // W_t2e
    load_W_tile(Wh2, Wl2, 4, tid);   // W_t2t
    load_X_split(Xh, Xl, tgt + (size_t)row0 * D, tid);
    __syncthreads();
    int tx = tid & 31, ty = tid >> 5;
    {
        float acc[8][4];
        gemm_mma(Xh, Xl, Wh1, Wl1, tid, acc);
        __syncthreads();
        stage_acc(Cs, acc, tid);
        __syncthreads();
        #pragma unroll
        for (int r = 0; r < 8; r++) {
            float4 v = *(float4*)(Cs + (ty * 8 + r) * LDC + tx * 4);
            *(float4*)(g_Pt + (size_t)(row0 + ty * 8 + r) * D + tx * 4) = v;
        }
        __syncthreads();
    }
    {
        float acc[8][4];
        gemm_mma(Xh, Xl, Wh2, Wl2, tid, acc);
        __syncthreads();
        stage_acc(Cs, acc, tid);
        __syncthreads();
        #pragma unroll
        for (int r = 0; r < 8; r++) {
            float4 v = *(float4*)(Cs + (ty * 8 + r) * LDC + tx * 4);
            *(float4*)(g_Ptt + (size_t)(row0 + ty * 8 + r) * D + tx * 4) = v;
        }
    }
}

// ---------------- kernel 3: d_bond = LN(silu(bond@W_e2e + gather(Ps) + gather(Pt))) ----------------
__global__ __launch_bounds__(256) void bond_kernel(const float* __restrict__ bond,
                                                   const float* __restrict__ g1,
                                                   const float* __restrict__ b1,
                                                   const int* __restrict__ src_order,
                                                   const int* __restrict__ tgt_order,
                                                   float* __restrict__ out0) {
    extern __shared__ char sm[];
    __nv_bfloat16* Xh = (__nv_bfloat16*)sm;
    __nv_bfloat16* Xl = Xh + 64 * LDS_T;
    __nv_bfloat16* Wh = Xl + 64 * LDS_T;
    __nv_bfloat16* Wl = Wh + D * LDS_T;
    float* Cs = (float*)sm;
    int tid = threadIdx.x;
    int row0 = blockIdx.x * 64;           // global row in [0, B*E)
    int b    = row0 / En;                 // tile never crosses batch (E % 64 == 0)
    load_W_tile(Wh, Wl, 2, tid);          // W_e2e
    load_X_split(Xh, Xl, bond + (size_t)row0 * D, tid);
    __syncthreads();
    float acc[8][4];
    gemm_mma(Xh, Xl, Wh, Wl, tid, acc);
    __syncthreads();
    stage_acc(Cs, acc, tid);
    __syncthreads();

    int tx = tid & 31, ty = tid >> 5;
    float gg[4], bb[4];
    #pragma unroll
    for (int c = 0; c < 4; c++) { gg[c] = g1[tx * 4 + c]; bb[c] = b1[tx * 4 + c]; }

    #pragma unroll
    for (int r = 0; r < 8; r++) {
        int row = row0 + ty * 8 + r;
        int e   = row - b * En;
        int so  = src_order[e];
        int to  = tgt_order[e];
        float4 cv = *(float4*)(Cs + (ty * 8 + r) * LDC + tx * 4);
        float4 ps = *(const float4*)(g_Ps + ((size_t)b * NSn + so) * D + tx * 4);
        float4 pt = *(const float4*)(g_Pt + ((size_t)b * NTn + to) * D + tx * 4);
        float v[4];
        v[0] = cv.x + ps.x + pt.x;
        v[1] = cv.y + ps.y + pt.y;
        v[2] = cv.z + ps.z + pt.z;
        v[3] = cv.w + ps.w + pt.w;
        float d[4];
        silu_ln(v, gg, bb, d);
        float4 xin = *(const float4*)(bond + (size_t)row * D + tx * 4);
        float4 db = {d[0], d[1], d[2], d[3]};
        float4 o0 = {xin.x + d[0], xin.y + d[1], xin.z + d[2], xin.w + d[3]};
        *(float4*)(g_db + (size_t)row * D + tx * 4) = db;
        *(float4*)(out0 + (size_t)row * D + tx * 4) = o0;
    }
}

// ---------------- kernel 4: bond_reduce = mean_k(coef * d_bond[edge_order]) ----------------
__global__ __launch_bounds__(256) void reduce_kernel(const int* __restrict__ edge_order,
                                                     const float* __restrict__ coef) {
    int tid  = threadIdx.x;
    int lane = tid & 31;
    int node = (blockIdx.x * blockDim.x + tid) >> 5;   // [0, B*NT)
    int b = node / NTn;
    int t = node - b * NTn;

    int   e_l = 0;
    float c_l = 0.0f;
    if (lane < Kc) {
        e_l = edge_order[t * Kc + lane];
        c_l = coef[t * Kc + lane];
    }
    float4 acc = {0.f, 0.f, 0.f, 0.f};
    #pragma unroll
    for (int k = 0; k < Kc; k++) {
        int   e = __shfl_sync(0xFFFFFFFFu, e_l, k);
        float c = __shfl_sync(0xFFFFFFFFu, c_l, k);
        float4 v = *(const float4*)(g_db + ((size_t)b * En + e) * D + lane * 4);
        acc.x += c * v.x;
        acc.y += c * v.y;
        acc.z += c * v.z;
        acc.w += c * v.w;
    }
    const float inv = 1.0f / Kc;
    acc.x *= inv; acc.y *= inv; acc.z *= inv; acc.w *= inv;
    *(float4*)(g_red + (size_t)node * D + lane * 4) = acc;
}

// ---------------- kernel 5: d_tgt = LN(silu(red@W_e2t + Ptt)) ; out = tgt + d_tgt ----------------
__global__ __launch_bounds__(256) void tgt_kernel(const float* __restrict__ tgt,
                                                  const float* __restrict__ g2,
                                                  const float* __restrict__ b2,
                                                  float* __restrict__ out2) {
    extern __shared__ char sm[];
    __nv_bfloat16* Xh = (__nv_bfloat16*)sm;
    __nv_bfloat16* Xl = Xh + 64 * LDS_T;
    __nv_bfloat16* Wh = Xl + 64 * LDS_T;
    __nv_bfloat16* Wl = Wh + D * LDS_T;
    float* Cs = (float*)sm;
    int tid = threadIdx.x;
    int row0 = blockIdx.x * 64;
    load_W_tile(Wh, Wl, 3, tid);          // W_e2t
    load_X_split(Xh, Xl, g_red + (size_t)row0 * D, tid);
    __syncthreads();
    float acc[8][4];
    gemm_mma(Xh, Xl, Wh, Wl, tid, acc);
    __syncthreads();
    stage_acc(Cs, acc, tid);
    __syncthreads();

    int tx = tid & 31, ty = tid >> 5;
    float gg[4], bb[4];
    #pragma unroll
    for (int c = 0; c < 4; c++) { gg[c] = g2[tx * 4 + c]; bb[c] = b2[tx * 4 + c]; }

    #pragma unroll
    for (int r = 0; r < 8; r++) {
        int row = row0 + ty * 8 + r;
        float4 cv = *(float4*)(Cs + (ty * 8 + r) * LDC + tx * 4);
        float4 pt = *(const float4*)(g_Ptt + (size_t)row * D + tx * 4);
        float v[4];
        v[0] = cv.x + pt.x;
        v[1] = cv.y + pt.y;
        v[2] = cv.z + pt.z;
        v[3] = cv.w + pt.w;
        float d[4];
        silu_ln(v, gg, bb, d);
        float4 tin = *(const float4*)(tgt + (size_t)row * D + tx * 4);
        float4 o2 = {tin.x + d[0], tin.y + d[1], tin.z + d[2], tin.w + d[3]};
        *(float4*)(out2 + (size_t)row * D + tx * 4) = o2;
    }
}

// ---------------- launch ----------------
extern "C" void kernel_launch(void* const* d_in, const int* in_sizes, int n_in,
                              void* d_out, int out_size) {
    const float* bond  = (const float*)d_in[0];
    const float* src   = (const float*)d_in[1];
    const float* tgt   = (const float*)d_in[2];
    const float* W_s2e = (const float*)d_in[3];
    const float* W_t2e = (const float*)d_in[4];
    const float* W_e2e = (const float*)d_in[5];
    const float* ln1_g = (const float*)d_in[6];
    const float* ln1_b = (const float*)d_in[7];
    const float* W_e2t = (const float*)d_in[8];
    const float* W_t2t = (const float*)d_in[9];
    const float* ln2_g = (const float*)d_in[10];
    const float* ln2_b = (const float*)d_in[11];
    const float* coef  = (const float*)d_in[12];
    const int*   so    = (const int*)d_in[13];
    const int*   to    = (const int*)d_in[14];
    const int*   eo    = (const int*)d_in[15];

    float* out  = (float*)d_out;
    float* out0 = out;                                   // bond + d_bond   [B,E,D]
    float* out1 = out0 + (size_t)Bn * En * D;            // src passthrough [B,NS,D]
    float* out2 = out1 + (size_t)Bn * NSn * D;           // tgt + d_tgt     [B,NT,D]

    cudaFuncSetAttribute(proj_src_kernel,      cudaFuncAttributeMaxDynamicSharedMemorySize, SM_SINGLE);
    cudaFuncSetAttribute(proj_tgt_dual_kernel, cudaFuncAttributeMaxDynamicSharedMemorySize, SM_DUAL);
    cudaFuncSetAttribute(bond_kernel,          cudaFuncAttributeMaxDynamicSharedMemorySize, SM_SINGLE);
    cudaFuncSetAttribute(tgt_kernel,           cudaFuncAttributeMaxDynamicSharedMemorySize, SM_SINGLE);

    // split weights (5 * 16384 elems, 320 blocks)
    prep_w_kernel<<<320, 256>>>(W_s2e, W_t2e, W_e2e, W_e2t, W_t2t);

    // node projections (independent)
    proj_src_kernel<<<(Bn * NSn) / 64, 256, SM_SINGLE>>>(src);
    proj_tgt_dual_kernel<<<(Bn * NTn) / 64, 256, SM_DUAL>>>(tgt);

    // src passthrough
    cudaMemcpyAsync(out1, src, (size_t)Bn * NSn * D * sizeof(float),
                    cudaMemcpyDeviceToDevice, 0);

    // node2bond + silu + LN
    bond_kernel<<<(Bn * En) / 64, 256, SM_SINGLE>>>(bond, ln1_g, ln1_b, so, to, out0);

    // bond2node weighted mean
    reduce_kernel<<<(Bn * NTn) / 8, 256>>>(eo, coef);

    // target update + silu + LN
    tgt_kernel<<<(Bn * NTn) / 64, 256, SM_SINGLE>>>(tgt, ln2_g, ln2_b, out2);
}